// round 3
// baseline (speedup 1.0000x reference)
#include <cuda_runtime.h>
#include <math_constants.h>

// 128x128 grid, 8 batch elements, channel = 1.
#define H 128
#define W 128
#define B 8
#define HW (H * W)

// Scratch: per-(row i, col w) squared vertical distance g(i,w)^2.
// __device__ global (no cudaMalloc allowed).
__device__ float g_g2[HW];

// K1: one block per column w; thread = row index.
// mask[h] = OR over batch of fm[b, h, w] > 0.5
// g(i,w) = min_{h: mask[h]} |i - h| ; store g^2 at g2[i*W + w]
__global__ void __launch_bounds__(H) edt_cols_kernel(const float* __restrict__ fm,
                                                     float* __restrict__ g2) {
    const int w = blockIdx.x;
    const int i = threadIdx.x;

    __shared__ unsigned char m[H];

    bool hit = false;
#pragma unroll
    for (int b = 0; b < B; b++) {
        hit |= (fm[b * HW + i * W + w] > 0.5f);
    }
    m[i] = hit ? 1 : 0;
    __syncthreads();

    int g = 1 << 20;
#pragma unroll 4
    for (int h = 0; h < H; h++) {
        if (m[h]) {
            int d = i - h;
            d = d < 0 ? -d : d;
            g = d < g ? d : g;
        }
    }
    float gf = (g >= (1 << 20)) ? CUDART_INF_F : (float)g;
    g2[i * W + w] = gf * gf;
}

// K2: one block per row i; thread = column j.
// D(i,j) = sqrt( min_w (j-w)^2 + g2[i,w] ), broadcast to all 8 batches.
__global__ void __launch_bounds__(W) edt_rows_kernel(const float* __restrict__ g2,
                                                     float* __restrict__ out) {
    const int i = blockIdx.x;
    const int j = threadIdx.x;

    __shared__ float s[W];
    s[j] = g2[i * W + j];
    __syncthreads();

    float d = CUDART_INF_F;
#pragma unroll 8
    for (int w = 0; w < W; w++) {
        float dj = (float)(j - w);
        d = fminf(d, fmaf(dj, dj, s[w]));
    }
    float r = sqrtf(d);

    const int base = i * W + j;
#pragma unroll
    for (int b = 0; b < B; b++) {
        out[b * HW + base] = r;
    }
}

extern "C" void kernel_launch(void* const* d_in, const int* in_sizes, int n_in,
                              void* d_out, int out_size) {
    const float* fm = (const float*)d_in[0];
    float* out = (float*)d_out;

    float* g2;
    cudaGetSymbolAddress((void**)&g2, g_g2);

    edt_cols_kernel<<<W, H>>>(fm, g2);
    edt_rows_kernel<<<H, W>>>(g2, out);
}